// round 11
// baseline (speedup 1.0000x reference)
#include <cuda_runtime.h>
#include <cuda_fp16.h>
#include <cuda_bf16.h>
#include <math.h>

#define T_STEPS 512
#define BATCH   32
#define IDIM    1024
#define HDIM    1024
#define GDIM    4096   // 4*HDIM

// ---------------- device scratch (no allocs allowed) ----------------
__device__ __half  g_x16[(size_t)T_STEPS * BATCH * IDIM];  // canonical fp16 x
__device__ __half  g_h016[BATCH * HDIM];
__device__ __half  g_c016[BATCH * HDIM];
__device__ __half  g_hrelay[(size_t)T_STEPS * BATCH * HDIM]; // fp16 h relay
__device__ __half  g_wih[(size_t)GDIM * IDIM];   // fp16 weight_ih
__device__ __half  g_whh16[(size_t)GDIM * HDIM]; // fp16 weight_hh
__device__ float   g_bias[GDIM];                 // bias_ih + bias_hh
__device__ float   g_gx[(size_t)T_STEPS * BATCH * GDIM]; // [T][B][4H] fp32
__device__ unsigned g_grp[8 * 32];               // 8 group counters, 128B apart
__device__ int     g_dtype;                      // 0=fp16, 1=bf16, 2=fp32

// ---------------- mma / ldmatrix helpers ----------------
__device__ __forceinline__ void mma_m16n8k16(
    float& c0, float& c1, float& c2, float& c3,
    unsigned a0, unsigned a1, unsigned a2, unsigned a3,
    unsigned b0, unsigned b1)
{
    asm volatile(
        "mma.sync.aligned.m16n8k16.row.col.f32.f16.f16.f32 "
        "{%0,%1,%2,%3},{%4,%5,%6,%7},{%8,%9},{%0,%1,%2,%3};\n"
        : "+f"(c0), "+f"(c1), "+f"(c2), "+f"(c3)
        : "r"(a0), "r"(a1), "r"(a2), "r"(a3), "r"(b0), "r"(b1));
}

__device__ __forceinline__ unsigned smem_u32(const void* p)
{
    return (unsigned)__cvta_generic_to_shared(p);
}

__device__ __forceinline__ void ldsm_x4(unsigned& r0, unsigned& r1,
                                        unsigned& r2, unsigned& r3,
                                        unsigned addr)
{
    asm volatile("ldmatrix.sync.aligned.m8n8.x4.shared.b16 {%0,%1,%2,%3}, [%4];\n"
                 : "=r"(r0), "=r"(r1), "=r"(r2), "=r"(r3) : "r"(addr));
}

// ---------------- cp.async helpers (gx_gemm only) ----------------
__device__ __forceinline__ void cp16(void* smem, const void* gmem)
{
    unsigned s = smem_u32(smem);
    asm volatile("cp.async.cg.shared.global [%0], [%1], 16;\n"
                 :: "r"(s), "l"(gmem) : "memory");
}
#define CP_COMMIT() asm volatile("cp.async.commit_group;\n" ::: "memory")
#define CP_WAIT(n)  asm volatile("cp.async.wait_group %0;\n" :: "n"(n) : "memory")

// ---------------- dtype detection on x ----------------
__global__ void detect_kernel(const void* __restrict__ x)
{
    __shared__ float red[3][256];
    const int tid = threadIdx.x;
    const unsigned short* p16 = (const unsigned short*)x;
    const unsigned*       p32 = (const unsigned*)x;

    g_grp[tid] = 0u;   // reset all 256 counter slots for this launch

    float a0 = 0.f, a1 = 0.f, a2 = 0.f;
    for (int i = tid; i < 4096; i += 256) {
        unsigned short b = p16[i];
        float f0 = __half2float(__ushort_as_half(b));
        float f1 = __bfloat162float(__ushort_as_bfloat16(b));
        a0 += isfinite(f0) ? fminf(fabsf(f0), 100.f) : 100.f;
        a1 += isfinite(f1) ? fminf(fabsf(f1), 100.f) : 100.f;
    }
    for (int i = tid; i < 2048; i += 256) {
        float f2 = __uint_as_float(p32[i]);
        a2 += isfinite(f2) ? fminf(fabsf(f2), 100.f) : 100.f;
    }
    red[0][tid] = a0; red[1][tid] = a1; red[2][tid] = a2;
    __syncthreads();
    for (int s = 128; s > 0; s >>= 1) {
        if (tid < s) {
            red[0][tid] += red[0][tid + s];
            red[1][tid] += red[1][tid + s];
            red[2][tid] += red[2][tid + s];
        }
        __syncthreads();
    }
    if (tid == 0) {
        float m0 = red[0][0] / 4096.f;
        float m1 = red[1][0] / 4096.f;
        float m2 = red[2][0] / 2048.f;
        const float tgt = 0.7979f;
        float d0 = fabsf(logf(fmaxf(m0, 1e-9f) / tgt));
        float d1 = fabsf(logf(fmaxf(m1, 1e-9f) / tgt));
        float d2 = fabsf(logf(fmaxf(m2, 1e-9f) / tgt));
        int dt = 0; float best = d0;
        if (d1 < best) { best = d1; dt = 1; }
        if (d2 < best) { dt = 2; }
        g_dtype = dt;
    }
}

__device__ __forceinline__ __half load16(const void* p, size_t i, int dt)
{
    if (dt == 0) return ((const __half*)p)[i];
    if (dt == 1) return __float2half(__bfloat162float(((const __nv_bfloat16*)p)[i]));
    return __float2half(((const float*)p)[i]);
}

// ---------------- canonicalize x, h0, c0 to fp16 ----------------
__global__ void convert_kernel(const void* __restrict__ x,
                               const void* __restrict__ h0,
                               const void* __restrict__ c0)
{
    const int dt = g_dtype;
    size_t i0 = (size_t)blockIdx.x * blockDim.x + threadIdx.x;
    size_t stride = (size_t)gridDim.x * blockDim.x;
    size_t n = (size_t)T_STEPS * BATCH * IDIM;
    for (size_t i = i0; i < n; i += stride) g_x16[i] = load16(x, i, dt);
    for (size_t i = i0; i < (size_t)BATCH * HDIM; i += stride) {
        g_h016[i] = load16(h0, i, dt);
        g_c016[i] = load16(c0, i, dt);
    }
}

// ---------------- prep: weights -> fp16, sum biases ----------------
__global__ void prep_kernel(const float* __restrict__ wih,
                            const float* __restrict__ whh,
                            const float* __restrict__ bih,
                            const float* __restrict__ bhh)
{
    size_t i = (size_t)blockIdx.x * blockDim.x + threadIdx.x;
    size_t n = (size_t)GDIM * IDIM;
    size_t stride = (size_t)gridDim.x * blockDim.x;
    for (size_t idx = i; idx < n; idx += stride) {
        g_wih[idx]   = __float2half(wih[idx]);
        g_whh16[idx] = __float2half(whh[idx]);
    }
    if (i < GDIM) g_bias[i] = bih[i] + bhh[i];
}

// ---------------- phase A: gx = x @ Wih^T + bias ----------------
#define BM 128
#define BN 64
#define BK 64
#define LDA (BK + 8)   // 72 halves
#define GX_STAGE (BM * LDA + BN * LDA)          // halves per stage
#define GX_SMEM  (2 * GX_STAGE * 2)             // bytes

__global__ __launch_bounds__(256) void gx_gemm()
{
    extern __shared__ __half gxs[];

    const int m0 = blockIdx.y * BM;
    const int n0 = blockIdx.x * BN;
    const int tid  = threadIdx.x;
    const int lane = tid & 31;
    const int w    = tid >> 5;
    const int wm   = w & 3;
    const int wn   = w >> 2;

    float acc[2][4][4];
#pragma unroll
    for (int mt = 0; mt < 2; mt++)
#pragma unroll
        for (int nt = 0; nt < 4; nt++)
#pragma unroll
            for (int e = 0; e < 4; e++) acc[mt][nt][e] = 0.f;

    const int g    = lane >> 2;
    const int coff = (lane & 3) * 2;

    const int nk = IDIM / BK;   // 16

    auto issue = [&](int kt, int s) {
        __half* As = gxs + s * GX_STAGE;
        __half* Bs = As + BM * LDA;
        int k0 = kt * BK;
#pragma unroll
        for (int j = 0; j < 4; j++) {
            int u = tid + j * 256;
            int r = u >> 3, c = u & 7;
            cp16(&As[r * LDA + c * 8],
                 &g_x16[(size_t)(m0 + r) * IDIM + k0 + c * 8]);
        }
#pragma unroll
        for (int j = 0; j < 2; j++) {
            int u = tid + j * 256;
            int r = u >> 3, c = u & 7;
            cp16(&Bs[r * LDA + c * 8],
                 &g_wih[(size_t)(n0 + r) * IDIM + k0 + c * 8]);
        }
    };

    issue(0, 0);
    CP_COMMIT();

    // ldmatrix lane addressing (precomputed pieces)
    const int a_r = (lane & 7) + ((lane & 8) ? 8 : 0);   // row within 16
    const int a_c = (lane & 16) ? 8 : 0;                 // k offset
    const int gr  = lane >> 3;
    const int b_r = ((gr & 2) ? 8 : 0) + (lane & 7);     // row within 16 (2 n-tiles)
    const int b_c = (gr & 1) ? 8 : 0;                    // k offset

    for (int kt = 0; kt < nk; kt++) {
        if (kt + 1 < nk) {
            issue(kt + 1, (kt + 1) & 1);
            CP_COMMIT();
            CP_WAIT(1);
        } else {
            CP_WAIT(0);
        }
        __syncthreads();

        const __half* As = gxs + (kt & 1) * GX_STAGE;
        const __half* Bs = As + BM * LDA;

#pragma unroll
        for (int ks = 0; ks < BK; ks += 16) {
            unsigned af[2][4];
#pragma unroll
            for (int mt = 0; mt < 2; mt++) {
                int row0 = wm * 32 + mt * 16;
                unsigned addr = smem_u32(&As[(row0 + a_r) * LDA + ks + a_c]);
                ldsm_x4(af[mt][0], af[mt][1], af[mt][2], af[mt][3], addr);
            }
            unsigned bf[4][2];
#pragma unroll
            for (int ntp = 0; ntp < 4; ntp += 2) {
                int nrow0 = wn * 32 + ntp * 8;
                unsigned addr = smem_u32(&Bs[(nrow0 + b_r) * LDA + ks + b_c]);
                ldsm_x4(bf[ntp][0], bf[ntp][1], bf[ntp + 1][0], bf[ntp + 1][1], addr);
            }
#pragma unroll
            for (int mt = 0; mt < 2; mt++)
#pragma unroll
                for (int nt = 0; nt < 4; nt++)
                    mma_m16n8k16(acc[mt][nt][0], acc[mt][nt][1],
                                 acc[mt][nt][2], acc[mt][nt][3],
                                 af[mt][0], af[mt][1], af[mt][2], af[mt][3],
                                 bf[nt][0], bf[nt][1]);
        }
        __syncthreads();
    }

#pragma unroll
    for (int mt = 0; mt < 2; mt++) {
#pragma unroll
        for (int nt = 0; nt < 4; nt++) {
            int row = m0 + wm * 32 + mt * 16 + g;
            int col = n0 + wn * 32 + nt * 8 + coff;
            float b0 = g_bias[col], b1 = g_bias[col + 1];
            g_gx[(size_t)row * GDIM + col]           = acc[mt][nt][0] + b0;
            g_gx[(size_t)row * GDIM + col + 1]       = acc[mt][nt][1] + b1;
            g_gx[(size_t)(row + 8) * GDIM + col]     = acc[mt][nt][2] + b0;
            g_gx[(size_t)(row + 8) * GDIM + col + 1] = acc[mt][nt][3] + b1;
        }
    }
}

// ---------------- phase B: persistent recurrent kernel ----------------
// 128 CTAs x 256 threads; CTA owns 8 hidden units (32 gate rows).
// W_hh fragments register-resident (8-way K-split across warps).
// GROUP-DEPENDENCY barrier: warp w's K slice [128w,128w+128) is produced by
// CTAs [16w,16w+16) only. Each CTA arrives at counter bid>>4 after its h
// slice is published; warp w polls counter w (target t*16) and proceeds
// independently — CTA skew overlaps instead of accumulating.
#define HWP   136                   // per-warp h slice stride (halves)
#define HWSZ  (32 * HWP)            // halves per warp slice
#define PSTR  36                    // partial tile row stride (floats)
#define PBUF  (32 * PSTR)           // floats per warp partial buffer
#define NBLK  128
#define SMEM_BYTES (8 * HWSZ * 2 + 8 * PBUF * 4)   // 69632 + 36864 = 106496

__global__ __launch_bounds__(256, 1) void lstm_kernel(void* __restrict__ out)
{
    extern __shared__ char smem_raw[];
    __half* h_all = (__half*)smem_raw;              // [8][32][HWP]
    float*  part  = (float*)(h_all + 8 * HWSZ);     // [8][32][PSTR]

    const int tid  = threadIdx.x;
    const int lane = tid & 31;
    const int w    = tid >> 5;
    const int bid  = blockIdx.x;
    const int dt   = g_dtype;

    const int g     = lane >> 2;
    const int coff4 = (lane & 3) * 2;
    const int kbase = w * 128;
    const int grp   = bid >> 4;                     // arrival counter index

    __half* h_w = h_all + w * HWSZ;

    // ---- one-time: load this warp's W_hh fragments (K slice of 128) ----
    unsigned a_frag[8][2][4];
    {
#pragma unroll
        for (int ki = 0; ki < 8; ki++) {
            int k = kbase + ki * 16;
#pragma unroll
            for (int mt = 0; mt < 2; mt++) {
                int r0 = mt * 16 + g;
                int r1 = r0 + 8;
                size_t row0 = (size_t)((r0 >> 3) * HDIM + bid * 8 + (r0 & 7));
                size_t row1 = (size_t)((r1 >> 3) * HDIM + bid * 8 + (r1 & 7));
                a_frag[ki][mt][0] = *(const unsigned*)&g_whh16[row0 * HDIM + k + coff4];
                a_frag[ki][mt][1] = *(const unsigned*)&g_whh16[row1 * HDIM + k + coff4];
                a_frag[ki][mt][2] = *(const unsigned*)&g_whh16[row0 * HDIM + k + 8 + coff4];
                a_frag[ki][mt][3] = *(const unsigned*)&g_whh16[row1 * HDIM + k + 8 + coff4];
            }
        }
    }

    // pointwise ownership: thread -> (batch b8, hidden hid within slice)
    const int b8  = tid >> 3;
    const int hid = tid & 7;
    const int hb  = bid * 8 + hid;
    float creg = __half2float(g_c016[b8 * HDIM + hb]);

    // ldmatrix B-frag lane addressing (validated in R8)
    const int gr  = lane >> 3;
    const int b_r = ((gr & 2) ? 8 : 0) + (lane & 7);
    const int b_c = (gr & 1) ? 8 : 0;

    const size_t y_sz  = (size_t)T_STEPS * BATCH * HDIM;
    const size_t bh_sz = (size_t)BATCH * HDIM;

    for (int t = 0; t < T_STEPS; t++) {
        // wait for this warp's 16 producer CTAs (skip t=0: h0 precomputed)
        if (t > 0) {
            if (lane == 0) {
                unsigned target = (unsigned)t * 16u;
                unsigned v, spins = 0;
                do {
                    asm volatile("ld.acquire.gpu.global.u32 %0, [%1];"
                                 : "=r"(v) : "l"(&g_grp[w * 32]) : "memory");
                    if (v >= target) break;
                } while (++spins < 2000000u);   // escape hatch
            }
            __syncwarp();
        }

        // warp-private h staging: 32 rows x 128 halves (uint4 LDG -> STS)
        const __half* hsrc = (t == 0) ? g_h016
                                      : (g_hrelay + (size_t)(t - 1) * bh_sz);
#pragma unroll
        for (int j = 0; j < 16; j++) {
            int idx = lane + j * 32;
            int row = idx >> 4;
            int col = idx & 15;
            uint4 v = *(const uint4*)&hsrc[(size_t)row * HDIM + kbase + col * 8];
            *(uint4*)&h_w[row * HWP + col * 8] = v;
        }
        __syncwarp();

        // prefetch gx
        size_t gxb = ((size_t)t * BATCH + b8) * GDIM;
        float gi = g_gx[gxb + 0 * HDIM + hb];
        float gf = g_gx[gxb + 1 * HDIM + hb];
        float gg = g_gx[gxb + 2 * HDIM + hb];
        float go = g_gx[gxb + 3 * HDIM + hb];

        // warp computes full 32x32 partial over its K slice
        float acc[2][4][4];
#pragma unroll
        for (int mt = 0; mt < 2; mt++)
#pragma unroll
            for (int nt = 0; nt < 4; nt++)
#pragma unroll
                for (int e = 0; e < 4; e++) acc[mt][nt][e] = 0.f;

#pragma unroll
        for (int ki = 0; ki < 8; ki++) {
            int kk = ki * 16;
            unsigned bf[4][2];
#pragma unroll
            for (int ntp = 0; ntp < 4; ntp += 2) {
                unsigned addr = smem_u32(&h_w[(ntp * 8 + b_r) * HWP + kk + b_c]);
                ldsm_x4(bf[ntp][0], bf[ntp][1], bf[ntp + 1][0], bf[ntp + 1][1], addr);
            }
#pragma unroll
            for (int mt = 0; mt < 2; mt++)
#pragma unroll
                for (int nt = 0; nt < 4; nt++)
                    mma_m16n8k16(acc[mt][nt][0], acc[mt][nt][1],
                                 acc[mt][nt][2], acc[mt][nt][3],
                                 a_frag[ki][mt][0], a_frag[ki][mt][1],
                                 a_frag[ki][mt][2], a_frag[ki][mt][3],
                                 bf[nt][0], bf[nt][1]);
        }

        // store partial tile
        float* pw = part + w * PBUF;
#pragma unroll
        for (int mt = 0; mt < 2; mt++)
#pragma unroll
            for (int nt = 0; nt < 4; nt++) {
                int row = mt * 16 + g;
                int col = nt * 8 + coff4;
                *(float2*)&pw[row * PSTR + col]       = make_float2(acc[mt][nt][0], acc[mt][nt][1]);
                *(float2*)&pw[(row + 8) * PSTR + col] = make_float2(acc[mt][nt][2], acc[mt][nt][3]);
            }
        __syncthreads();

        // fused reduce + pointwise
        float gate[4] = {gi, gf, gg, go};
#pragma unroll
        for (int q = 0; q < 4; q++) {
            int row = q * 8 + hid;
#pragma unroll
            for (int j = 0; j < 8; j++)
                gate[q] += part[j * PBUF + row * PSTR + b8];
        }
        float si = 1.f / (1.f + expf(-gate[0]));
        float sf = 1.f / (1.f + expf(-gate[1]));
        float tg = tanhf(gate[2]);
        float so = 1.f / (1.f + expf(-gate[3]));
        float cnew = sf * creg + si * tg;
        float hnew = so * tanhf(cnew);
        __half h16 = __float2half(hnew);
        __half c16 = __float2half(cnew);
        creg = __half2float(c16);

        size_t idx = ((size_t)t * BATCH + b8) * HDIM + hb;
        g_hrelay[idx] = h16;

        float hf = __half2float(h16);
        if (dt == 0)      ((__half*)out)[idx] = h16;
        else if (dt == 1) ((__nv_bfloat16*)out)[idx] = __float2bfloat16(hf);
        else              ((float*)out)[idx] = hf;

        if (t == T_STEPS - 1) {
            size_t hidx = y_sz + (size_t)b8 * HDIM + hb;
            size_t cidx = hidx + bh_sz;
            float cf = __half2float(c16);
            if (dt == 0) {
                ((__half*)out)[hidx] = h16;
                ((__half*)out)[cidx] = c16;
            } else if (dt == 1) {
                ((__nv_bfloat16*)out)[hidx] = __float2bfloat16(hf);
                ((__nv_bfloat16*)out)[cidx] = __float2bfloat16(cf);
            } else {
                ((float*)out)[hidx] = hf;
                ((float*)out)[cidx] = cf;
            }
        }

        // publish: block sync (all h writes done), then one arrival at this
        // CTA's group counter (fence orders the h stores for acquire readers)
        __syncthreads();
        if (t < T_STEPS - 1) {
            if (tid == 0) {
                __threadfence();
                atomicAdd(&g_grp[grp * 32], 1u);
            }
        }
    }
}

// ---------------- launch ----------------
extern "C" void kernel_launch(void* const* d_in, const int* in_sizes, int n_in,
                              void* d_out, int out_size)
{
    const void*  x   = d_in[0];
    const void*  h0  = d_in[1];
    const void*  c0  = d_in[2];
    const float* wih = (const float*)d_in[3];
    const float* whh = (const float*)d_in[4];
    const float* bih = (const float*)d_in[5];
    const float* bhh = (const float*)d_in[6];

    cudaFuncSetAttribute(lstm_kernel,
                         cudaFuncAttributeMaxDynamicSharedMemorySize,
                         SMEM_BYTES);
    cudaFuncSetAttribute(gx_gemm,
                         cudaFuncAttributeMaxDynamicSharedMemorySize,
                         GX_SMEM);

    detect_kernel<<<1, 256>>>(x);
    prep_kernel<<<1024, 256>>>(wih, whh, bih, bhh);
    convert_kernel<<<2048, 256>>>(x, h0, c0);

    dim3 ggrid(GDIM / BN, (T_STEPS * BATCH) / BM);   // (64, 128)
    gx_gemm<<<ggrid, 256, GX_SMEM>>>();

    lstm_kernel<<<NBLK, 256, SMEM_BYTES>>>(d_out);
}

// round 12
// speedup vs baseline: 1.0542x; 1.0542x over previous
#include <cuda_runtime.h>
#include <cuda_fp16.h>
#include <cuda_bf16.h>
#include <math.h>

#define T_STEPS 512
#define BATCH   32
#define IDIM    1024
#define HDIM    1024
#define GDIM    4096   // 4*HDIM

// ---------------- device scratch (no allocs allowed) ----------------
__device__ __half  g_x16[(size_t)T_STEPS * BATCH * IDIM];  // canonical fp16 x
__device__ __half  g_h016[BATCH * HDIM];
__device__ __half  g_c016[BATCH * HDIM];
__device__ __half  g_hrelay[(size_t)T_STEPS * BATCH * HDIM]; // fp16 h relay
__device__ __half  g_wih[(size_t)GDIM * IDIM];   // fp16 weight_ih
__device__ __half  g_whh16[(size_t)GDIM * HDIM]; // fp16 weight_hh
__device__ float   g_bias[GDIM];                 // bias_ih + bias_hh
__device__ unsigned g_bar;                       // grid barrier counter
__device__ int     g_dtype;                      // 0=fp16, 1=bf16, 2=fp32

// ---------------- mma / ldmatrix helpers ----------------
__device__ __forceinline__ void mma_m16n8k16(
    float& c0, float& c1, float& c2, float& c3,
    unsigned a0, unsigned a1, unsigned a2, unsigned a3,
    unsigned b0, unsigned b1)
{
    asm volatile(
        "mma.sync.aligned.m16n8k16.row.col.f32.f16.f16.f32 "
        "{%0,%1,%2,%3},{%4,%5,%6,%7},{%8,%9},{%0,%1,%2,%3};\n"
        : "+f"(c0), "+f"(c1), "+f"(c2), "+f"(c3)
        : "r"(a0), "r"(a1), "r"(a2), "r"(a3), "r"(b0), "r"(b1));
}

__device__ __forceinline__ unsigned smem_u32(const void* p)
{
    return (unsigned)__cvta_generic_to_shared(p);
}

__device__ __forceinline__ void ldsm_x4(unsigned& r0, unsigned& r1,
                                        unsigned& r2, unsigned& r3,
                                        unsigned addr)
{
    asm volatile("ldmatrix.sync.aligned.m8n8.x4.shared.b16 {%0,%1,%2,%3}, [%4];\n"
                 : "=r"(r0), "=r"(r1), "=r"(r2), "=r"(r3) : "r"(addr));
}

// ---------------- dtype detection on x ----------------
__global__ void detect_kernel(const void* __restrict__ x)
{
    __shared__ float red[3][256];
    const int tid = threadIdx.x;
    const unsigned short* p16 = (const unsigned short*)x;
    const unsigned*       p32 = (const unsigned*)x;

    float a0 = 0.f, a1 = 0.f, a2 = 0.f;
    for (int i = tid; i < 4096; i += 256) {
        unsigned short b = p16[i];
        float f0 = __half2float(__ushort_as_half(b));
        float f1 = __bfloat162float(__ushort_as_bfloat16(b));
        a0 += isfinite(f0) ? fminf(fabsf(f0), 100.f) : 100.f;
        a1 += isfinite(f1) ? fminf(fabsf(f1), 100.f) : 100.f;
    }
    for (int i = tid; i < 2048; i += 256) {
        float f2 = __uint_as_float(p32[i]);
        a2 += isfinite(f2) ? fminf(fabsf(f2), 100.f) : 100.f;
    }
    red[0][tid] = a0; red[1][tid] = a1; red[2][tid] = a2;
    __syncthreads();
    for (int s = 128; s > 0; s >>= 1) {
        if (tid < s) {
            red[0][tid] += red[0][tid + s];
            red[1][tid] += red[1][tid + s];
            red[2][tid] += red[2][tid + s];
        }
        __syncthreads();
    }
    if (tid == 0) {
        float m0 = red[0][0] / 4096.f;
        float m1 = red[1][0] / 4096.f;
        float m2 = red[2][0] / 2048.f;
        const float tgt = 0.7979f;
        float d0 = fabsf(logf(fmaxf(m0, 1e-9f) / tgt));
        float d1 = fabsf(logf(fmaxf(m1, 1e-9f) / tgt));
        float d2 = fabsf(logf(fmaxf(m2, 1e-9f) / tgt));
        int dt = 0; float best = d0;
        if (d1 < best) { best = d1; dt = 1; }
        if (d2 < best) { dt = 2; }
        g_dtype = dt;
        g_bar = 0u;   // reset grid barrier for this launch
    }
}

__device__ __forceinline__ __half load16(const void* p, size_t i, int dt)
{
    if (dt == 0) return ((const __half*)p)[i];
    if (dt == 1) return __float2half(__bfloat162float(((const __nv_bfloat16*)p)[i]));
    return __float2half(((const float*)p)[i]);
}

// ---------------- canonicalize x, h0, c0 to fp16 ----------------
__global__ void convert_kernel(const void* __restrict__ x,
                               const void* __restrict__ h0,
                               const void* __restrict__ c0)
{
    const int dt = g_dtype;
    size_t i0 = (size_t)blockIdx.x * blockDim.x + threadIdx.x;
    size_t stride = (size_t)gridDim.x * blockDim.x;
    size_t n = (size_t)T_STEPS * BATCH * IDIM;
    for (size_t i = i0; i < n; i += stride) g_x16[i] = load16(x, i, dt);
    for (size_t i = i0; i < (size_t)BATCH * HDIM; i += stride) {
        g_h016[i] = load16(h0, i, dt);
        g_c016[i] = load16(c0, i, dt);
    }
}

// ---------------- prep: weights -> fp16, sum biases ----------------
__global__ void prep_kernel(const float* __restrict__ wih,
                            const float* __restrict__ whh,
                            const float* __restrict__ bih,
                            const float* __restrict__ bhh)
{
    size_t i = (size_t)blockIdx.x * blockDim.x + threadIdx.x;
    size_t n = (size_t)GDIM * IDIM;
    size_t stride = (size_t)gridDim.x * blockDim.x;
    for (size_t idx = i; idx < n; idx += stride) {
        g_wih[idx]   = __float2half(wih[idx]);
        g_whh16[idx] = __float2half(whh[idx]);
    }
    if (i < GDIM) g_bias[i] = bih[i] + bhh[i];
}

// ---------------- fused persistent LSTM kernel ----------------
// 128 CTAs x 256 threads; CTA owns 8 hidden units (32 gate rows of BOTH
// W_hh and W_ih). Per step t:
//   gates = W_ih_slice @ x[t] + W_hh_slice @ h[t-1] + bias  (one fp32 acc)
// The x-mma for step t+1 runs INSIDE the grid-barrier wait window (after
// this CTA's arrival, before poll-detect) — hiding the entire former
// gx_gemm phase in cycles that were previously idle spinning.
// W_hh frags register-resident; W_ih slice in smem (ldmatrix per step).
#define WIHP  1032                  // W_ih smem row stride (halves)
#define HWP   136                   // per-warp stage-buffer stride (halves)
#define HWSZ  (32 * HWP)            // halves per warp buffer
#define PSTR  36                    // partial tile row stride (floats)
#define PBUF  (32 * PSTR)           // floats per warp partial buffer
#define NBLK  128
// smem: wih_s 66048B + stage 69632B + part 36864B = 172544B
#define SMEM_BYTES (32 * WIHP * 2 + 8 * HWSZ * 2 + 8 * PBUF * 4)

__global__ __launch_bounds__(256, 1) void lstm_kernel(void* __restrict__ out)
{
    extern __shared__ char smem_raw[];
    __half* wih_s = (__half*)smem_raw;               // [32][WIHP]
    __half* h_all = wih_s + 32 * WIHP;               // [8][32][HWP] (x/h reuse)
    float*  part  = (float*)(h_all + 8 * HWSZ);      // [8][32][PSTR]

    const int tid  = threadIdx.x;
    const int lane = tid & 31;
    const int w    = tid >> 5;
    const int bid  = blockIdx.x;
    const int dt   = g_dtype;

    const int g     = lane >> 2;
    const int coff4 = (lane & 3) * 2;
    const int kbase = w * 128;

    __half* h_w = h_all + w * HWSZ;

    // ---- one-time: stage W_ih slice (32 gate rows) into smem ----
    // smem row rs -> global gate row (rs>>3)*HDIM + bid*8 + (rs&7)
#pragma unroll
    for (int j = 0; j < 16; j++) {
        int u  = tid + j * 256;       // 0..4095 uint4
        int rs = u >> 7;              // 0..31
        int c  = u & 127;             // uint4 index in row
        int grow = (rs >> 3) * HDIM + bid * 8 + (rs & 7);
        *(uint4*)&wih_s[rs * WIHP + c * 8] =
            *(const uint4*)&g_wih[(size_t)grow * IDIM + c * 8];
    }

    // ---- one-time: W_hh fragments (K slice of 128) in registers ----
    unsigned a_frag[8][2][4];
#pragma unroll
    for (int ki = 0; ki < 8; ki++) {
        int k = kbase + ki * 16;
#pragma unroll
        for (int mt = 0; mt < 2; mt++) {
            int r0 = mt * 16 + g;
            int r1 = r0 + 8;
            size_t row0 = (size_t)((r0 >> 3) * HDIM + bid * 8 + (r0 & 7));
            size_t row1 = (size_t)((r1 >> 3) * HDIM + bid * 8 + (r1 & 7));
            a_frag[ki][mt][0] = *(const unsigned*)&g_whh16[row0 * HDIM + k + coff4];
            a_frag[ki][mt][1] = *(const unsigned*)&g_whh16[row1 * HDIM + k + coff4];
            a_frag[ki][mt][2] = *(const unsigned*)&g_whh16[row0 * HDIM + k + 8 + coff4];
            a_frag[ki][mt][3] = *(const unsigned*)&g_whh16[row1 * HDIM + k + 8 + coff4];
        }
    }

    // pointwise ownership: thread -> (batch b8, hidden hid within slice)
    const int b8  = tid >> 3;
    const int hid = tid & 7;
    const int hb  = bid * 8 + hid;
    float creg = __half2float(g_c016[b8 * HDIM + hb]);
    float bias4[4];
#pragma unroll
    for (int q = 0; q < 4; q++) bias4[q] = g_bias[q * HDIM + hb];

    // ldmatrix lane addressing (validated in R8)
    const int a_r = (lane & 7) + ((lane & 8) ? 8 : 0);
    const int a_c = (lane & 16) ? 8 : 0;
    const int gr  = lane >> 3;
    const int b_r = ((gr & 2) ? 8 : 0) + (lane & 7);
    const int b_c = (gr & 1) ? 8 : 0;

    const size_t y_sz  = (size_t)T_STEPS * BATCH * HDIM;
    const size_t bh_sz = (size_t)BATCH * HDIM;

    __syncthreads();   // wih_s ready

    float acc[2][4][4];

    // x-mma for a given timestep into acc (acc zeroed here).
    auto do_x_mma = [&](int t) {
        const __half* xsrc = g_x16 + (size_t)t * BATCH * IDIM;
#pragma unroll
        for (int j = 0; j < 16; j++) {
            int idx = lane + j * 32;
            int row = idx >> 4;
            int col = idx & 15;
            uint4 v = *(const uint4*)&xsrc[(size_t)row * IDIM + kbase + col * 8];
            *(uint4*)&h_w[row * HWP + col * 8] = v;
        }
        __syncwarp();
#pragma unroll
        for (int mt = 0; mt < 2; mt++)
#pragma unroll
            for (int nt = 0; nt < 4; nt++)
#pragma unroll
                for (int e = 0; e < 4; e++) acc[mt][nt][e] = 0.f;
#pragma unroll
        for (int ki = 0; ki < 8; ki++) {
            int kk = ki * 16;
            unsigned af[2][4];
#pragma unroll
            for (int mt = 0; mt < 2; mt++) {
                unsigned addr = smem_u32(&wih_s[(mt * 16 + a_r) * WIHP
                                                + kbase + kk + a_c]);
                ldsm_x4(af[mt][0], af[mt][1], af[mt][2], af[mt][3], addr);
            }
            unsigned bf[4][2];
#pragma unroll
            for (int ntp = 0; ntp < 4; ntp += 2) {
                unsigned addr = smem_u32(&h_w[(ntp * 8 + b_r) * HWP + kk + b_c]);
                ldsm_x4(bf[ntp][0], bf[ntp][1], bf[ntp + 1][0], bf[ntp + 1][1], addr);
            }
#pragma unroll
            for (int mt = 0; mt < 2; mt++)
#pragma unroll
                for (int nt = 0; nt < 4; nt++)
                    mma_m16n8k16(acc[mt][nt][0], acc[mt][nt][1],
                                 acc[mt][nt][2], acc[mt][nt][3],
                                 af[mt][0], af[mt][1], af[mt][2], af[mt][3],
                                 bf[nt][0], bf[nt][1]);
        }
        __syncwarp();   // buffer free for h staging
    };

    do_x_mma(0);   // x contribution for t=0 (no dependency)

    for (int t = 0; t < T_STEPS; t++) {
        // stage h(t-1) into warp buffer (h(t-1) visibility guaranteed by
        // the barrier at the end of the previous iteration)
        const __half* hsrc = (t == 0) ? g_h016
                                      : (g_hrelay + (size_t)(t - 1) * bh_sz);
#pragma unroll
        for (int j = 0; j < 16; j++) {
            int idx = lane + j * 32;
            int row = idx >> 4;
            int col = idx & 15;
            uint4 v = *(const uint4*)&hsrc[(size_t)row * HDIM + kbase + col * 8];
            *(uint4*)&h_w[row * HWP + col * 8] = v;
        }
        __syncwarp();

        // h-mma accumulating on top of the x contribution
#pragma unroll
        for (int ki = 0; ki < 8; ki++) {
            int kk = ki * 16;
            unsigned bf[4][2];
#pragma unroll
            for (int ntp = 0; ntp < 4; ntp += 2) {
                unsigned addr = smem_u32(&h_w[(ntp * 8 + b_r) * HWP + kk + b_c]);
                ldsm_x4(bf[ntp][0], bf[ntp][1], bf[ntp + 1][0], bf[ntp + 1][1], addr);
            }
#pragma unroll
            for (int mt = 0; mt < 2; mt++)
#pragma unroll
                for (int nt = 0; nt < 4; nt++)
                    mma_m16n8k16(acc[mt][nt][0], acc[mt][nt][1],
                                 acc[mt][nt][2], acc[mt][nt][3],
                                 a_frag[ki][mt][0], a_frag[ki][mt][1],
                                 a_frag[ki][mt][2], a_frag[ki][mt][3],
                                 bf[nt][0], bf[nt][1]);
        }

        // store partial tile
        float* pw = part + w * PBUF;
#pragma unroll
        for (int mt = 0; mt < 2; mt++)
#pragma unroll
            for (int nt = 0; nt < 4; nt++) {
                int row = mt * 16 + g;
                int col = nt * 8 + coff4;
                *(float2*)&pw[row * PSTR + col]       = make_float2(acc[mt][nt][0], acc[mt][nt][1]);
                *(float2*)&pw[(row + 8) * PSTR + col] = make_float2(acc[mt][nt][2], acc[mt][nt][3]);
            }
        __syncthreads();

        // fused reduce + bias + pointwise
        float gate[4] = {bias4[0], bias4[1], bias4[2], bias4[3]};
#pragma unroll
        for (int q = 0; q < 4; q++) {
            int row = q * 8 + hid;
#pragma unroll
            for (int j = 0; j < 8; j++)
                gate[q] += part[j * PBUF + row * PSTR + b8];
        }
        float si = 1.f / (1.f + expf(-gate[0]));
        float sf = 1.f / (1.f + expf(-gate[1]));
        float tg = tanhf(gate[2]);
        float so = 1.f / (1.f + expf(-gate[3]));
        float cnew = sf * creg + si * tg;
        float hnew = so * tanhf(cnew);
        __half h16 = __float2half(hnew);
        __half c16 = __float2half(cnew);
        creg = __half2float(c16);

        size_t idx = ((size_t)t * BATCH + b8) * HDIM + hb;
        g_hrelay[idx] = h16;

        float hf = __half2float(h16);
        if (dt == 0)      ((__half*)out)[idx] = h16;
        else if (dt == 1) ((__nv_bfloat16*)out)[idx] = __float2bfloat16(hf);
        else              ((float*)out)[idx] = hf;

        if (t == T_STEPS - 1) {
            size_t hidx = y_sz + (size_t)b8 * HDIM + hb;
            size_t cidx = hidx + bh_sz;
            float cf = __half2float(c16);
            if (dt == 0) {
                ((__half*)out)[hidx] = h16;
                ((__half*)out)[cidx] = c16;
            } else if (dt == 1) {
                ((__nv_bfloat16*)out)[hidx] = __float2bfloat16(hf);
                ((__nv_bfloat16*)out)[cidx] = __float2bfloat16(cf);
            } else {
                ((float*)out)[hidx] = hf;
                ((float*)out)[cidx] = cf;
            }
        }

        // grid barrier with the NEXT step's x-mma hidden in the wait window:
        // fence+sync, arrive promptly, then all warps do x-stage+x-mma(t+1)
        // while other CTAs arrive, then tid0 detects, block sync releases.
        if (t < T_STEPS - 1) {
            __threadfence();
            __syncthreads();
            if (tid == 0) atomicAdd(&g_bar, 1u);
            do_x_mma(t + 1);                 // overlaps other CTAs' arrivals
            if (tid == 0) {
                unsigned target = (unsigned)(t + 1) * NBLK;
                unsigned v, spins = 0;
                do {
                    asm volatile("ld.acquire.gpu.global.u32 %0, [%1];"
                                 : "=r"(v) : "l"(&g_bar) : "memory");
                    if (v >= target) break;
                } while (++spins < 4000000u);   // escape hatch
            }
            __syncthreads();
        }
    }
}

// ---------------- launch ----------------
extern "C" void kernel_launch(void* const* d_in, const int* in_sizes, int n_in,
                              void* d_out, int out_size)
{
    const void*  x   = d_in[0];
    const void*  h0  = d_in[1];
    const void*  c0  = d_in[2];
    const float* wih = (const float*)d_in[3];
    const float* whh = (const float*)d_in[4];
    const float* bih = (const float*)d_in[5];
    const float* bhh = (const float*)d_in[6];

    cudaFuncSetAttribute(lstm_kernel,
                         cudaFuncAttributeMaxDynamicSharedMemorySize,
                         SMEM_BYTES);

    detect_kernel<<<1, 256>>>(x);
    prep_kernel<<<1024, 256>>>(wih, whh, bih, bhh);
    convert_kernel<<<2048, 256>>>(x, h0, c0);

    lstm_kernel<<<NBLK, 256, SMEM_BYTES>>>(d_out);
}

// round 13
// speedup vs baseline: 1.1233x; 1.0655x over previous
#include <cuda_runtime.h>
#include <cuda_fp16.h>
#include <cuda_bf16.h>
#include <math.h>

#define T_STEPS 512
#define BATCH   32
#define IDIM    1024
#define HDIM    1024
#define GDIM    4096   // 4*HDIM

// ---------------- device scratch (no allocs allowed) ----------------
__device__ __half  g_x16[(size_t)T_STEPS * BATCH * IDIM];  // canonical fp16 x
__device__ __half  g_h016[BATCH * HDIM];
__device__ __half  g_c016[BATCH * HDIM];
__device__ __half  g_hrelay[(size_t)T_STEPS * BATCH * HDIM]; // fp16 h relay
__device__ __half  g_wih[(size_t)GDIM * IDIM];   // fp16 weight_ih
__device__ __half  g_whh16[(size_t)GDIM * HDIM]; // fp16 weight_hh
__device__ float   g_bias[GDIM];                 // bias_ih + bias_hh
__device__ unsigned g_bar;                       // grid barrier counter
__device__ int     g_dtype;                      // 0=fp16, 1=bf16, 2=fp32

// ---------------- mma / ldmatrix helpers ----------------
__device__ __forceinline__ void mma_m16n8k16(
    float& c0, float& c1, float& c2, float& c3,
    unsigned a0, unsigned a1, unsigned a2, unsigned a3,
    unsigned b0, unsigned b1)
{
    asm volatile(
        "mma.sync.aligned.m16n8k16.row.col.f32.f16.f16.f32 "
        "{%0,%1,%2,%3},{%4,%5,%6,%7},{%8,%9},{%0,%1,%2,%3};\n"
        : "+f"(c0), "+f"(c1), "+f"(c2), "+f"(c3)
        : "r"(a0), "r"(a1), "r"(a2), "r"(a3), "r"(b0), "r"(b1));
}

__device__ __forceinline__ unsigned smem_u32(const void* p)
{
    return (unsigned)__cvta_generic_to_shared(p);
}

__device__ __forceinline__ void ldsm_x4(unsigned& r0, unsigned& r1,
                                        unsigned& r2, unsigned& r3,
                                        unsigned addr)
{
    asm volatile("ldmatrix.sync.aligned.m8n8.x4.shared.b16 {%0,%1,%2,%3}, [%4];\n"
                 : "=r"(r0), "=r"(r1), "=r"(r2), "=r"(r3) : "r"(addr));
}

// ---------------- dtype detection on x ----------------
__global__ void detect_kernel(const void* __restrict__ x)
{
    __shared__ float red[3][256];
    const int tid = threadIdx.x;
    const unsigned short* p16 = (const unsigned short*)x;
    const unsigned*       p32 = (const unsigned*)x;

    float a0 = 0.f, a1 = 0.f, a2 = 0.f;
    for (int i = tid; i < 4096; i += 256) {
        unsigned short b = p16[i];
        float f0 = __half2float(__ushort_as_half(b));
        float f1 = __bfloat162float(__ushort_as_bfloat16(b));
        a0 += isfinite(f0) ? fminf(fabsf(f0), 100.f) : 100.f;
        a1 += isfinite(f1) ? fminf(fabsf(f1), 100.f) : 100.f;
    }
    for (int i = tid; i < 2048; i += 256) {
        float f2 = __uint_as_float(p32[i]);
        a2 += isfinite(f2) ? fminf(fabsf(f2), 100.f) : 100.f;
    }
    red[0][tid] = a0; red[1][tid] = a1; red[2][tid] = a2;
    __syncthreads();
    for (int s = 128; s > 0; s >>= 1) {
        if (tid < s) {
            red[0][tid] += red[0][tid + s];
            red[1][tid] += red[1][tid + s];
            red[2][tid] += red[2][tid + s];
        }
        __syncthreads();
    }
    if (tid == 0) {
        float m0 = red[0][0] / 4096.f;
        float m1 = red[1][0] / 4096.f;
        float m2 = red[2][0] / 2048.f;
        const float tgt = 0.7979f;
        float d0 = fabsf(logf(fmaxf(m0, 1e-9f) / tgt));
        float d1 = fabsf(logf(fmaxf(m1, 1e-9f) / tgt));
        float d2 = fabsf(logf(fmaxf(m2, 1e-9f) / tgt));
        int dt = 0; float best = d0;
        if (d1 < best) { best = d1; dt = 1; }
        if (d2 < best) { dt = 2; }
        g_dtype = dt;
        g_bar = 0u;   // reset grid barrier for this launch
    }
}

__device__ __forceinline__ __half load16(const void* p, size_t i, int dt)
{
    if (dt == 0) return ((const __half*)p)[i];
    if (dt == 1) return __float2half(__bfloat162float(((const __nv_bfloat16*)p)[i]));
    return __float2half(((const float*)p)[i]);
}

// ---------------- canonicalize x, h0, c0 to fp16 ----------------
__global__ void convert_kernel(const void* __restrict__ x,
                               const void* __restrict__ h0,
                               const void* __restrict__ c0)
{
    const int dt = g_dtype;
    size_t i0 = (size_t)blockIdx.x * blockDim.x + threadIdx.x;
    size_t stride = (size_t)gridDim.x * blockDim.x;
    size_t n = (size_t)T_STEPS * BATCH * IDIM;
    for (size_t i = i0; i < n; i += stride) g_x16[i] = load16(x, i, dt);
    for (size_t i = i0; i < (size_t)BATCH * HDIM; i += stride) {
        g_h016[i] = load16(h0, i, dt);
        g_c016[i] = load16(c0, i, dt);
    }
}

// ---------------- prep: weights -> fp16, sum biases ----------------
__global__ void prep_kernel(const float* __restrict__ wih,
                            const float* __restrict__ whh,
                            const float* __restrict__ bih,
                            const float* __restrict__ bhh)
{
    size_t i = (size_t)blockIdx.x * blockDim.x + threadIdx.x;
    size_t n = (size_t)GDIM * IDIM;
    size_t stride = (size_t)gridDim.x * blockDim.x;
    for (size_t idx = i; idx < n; idx += stride) {
        g_wih[idx]   = __float2half(wih[idx]);
        g_whh16[idx] = __float2half(whh[idx]);
    }
    if (i < GDIM) g_bias[i] = bih[i] + bhh[i];
}

// ---------------- fused persistent LSTM kernel ----------------
// 128 CTAs x 256 threads; CTA owns 8 hidden units (32 gate rows of BOTH
// W_hh and W_ih).  gates = W_ih@x[t] + W_hh@h[t-1] + bias in one fp32 acc.
// x staging for t+1 issues BEFORE the reduce (latency hidden under reduce
// compute); the x-mma math runs inside the barrier wait window. Arrival is
// a single red.release.gpu (syncthreads establishes happens-before for all
// threads' h stores — no separate threadfence needed).
#define WIHP  1032                  // W_ih smem row stride (halves)
#define HWP   136                   // per-warp stage-buffer stride (halves)
#define HWSZ  (32 * HWP)            // halves per warp buffer
#define PSTR  36                    // partial tile row stride (floats)
#define PBUF  (32 * PSTR)           // floats per warp partial buffer
#define NBLK  128
// smem: wih_s 66048B + stage 69632B + part 36864B = 172544B
#define SMEM_BYTES (32 * WIHP * 2 + 8 * HWSZ * 2 + 8 * PBUF * 4)

__global__ __launch_bounds__(256, 1) void lstm_kernel(void* __restrict__ out)
{
    extern __shared__ char smem_raw[];
    __half* wih_s = (__half*)smem_raw;               // [32][WIHP]
    __half* h_all = wih_s + 32 * WIHP;               // [8][32][HWP] (x/h reuse)
    float*  part  = (float*)(h_all + 8 * HWSZ);      // [8][32][PSTR]

    const int tid  = threadIdx.x;
    const int lane = tid & 31;
    const int w    = tid >> 5;
    const int bid  = blockIdx.x;
    const int dt   = g_dtype;

    const int g     = lane >> 2;
    const int coff4 = (lane & 3) * 2;
    const int kbase = w * 128;

    __half* h_w = h_all + w * HWSZ;

    // ---- one-time: stage W_ih slice (32 gate rows) into smem ----
#pragma unroll
    for (int j = 0; j < 16; j++) {
        int u  = tid + j * 256;       // 0..4095 uint4
        int rs = u >> 7;              // 0..31
        int c  = u & 127;             // uint4 index in row
        int grow = (rs >> 3) * HDIM + bid * 8 + (rs & 7);
        *(uint4*)&wih_s[rs * WIHP + c * 8] =
            *(const uint4*)&g_wih[(size_t)grow * IDIM + c * 8];
    }

    // ---- one-time: W_hh fragments (K slice of 128) in registers ----
    unsigned a_frag[8][2][4];
#pragma unroll
    for (int ki = 0; ki < 8; ki++) {
        int k = kbase + ki * 16;
#pragma unroll
        for (int mt = 0; mt < 2; mt++) {
            int r0 = mt * 16 + g;
            int r1 = r0 + 8;
            size_t row0 = (size_t)((r0 >> 3) * HDIM + bid * 8 + (r0 & 7));
            size_t row1 = (size_t)((r1 >> 3) * HDIM + bid * 8 + (r1 & 7));
            a_frag[ki][mt][0] = *(const unsigned*)&g_whh16[row0 * HDIM + k + coff4];
            a_frag[ki][mt][1] = *(const unsigned*)&g_whh16[row1 * HDIM + k + coff4];
            a_frag[ki][mt][2] = *(const unsigned*)&g_whh16[row0 * HDIM + k + 8 + coff4];
            a_frag[ki][mt][3] = *(const unsigned*)&g_whh16[row1 * HDIM + k + 8 + coff4];
        }
    }

    // pointwise ownership: thread -> (batch b8, hidden hid within slice)
    const int b8  = tid >> 3;
    const int hid = tid & 7;
    const int hb  = bid * 8 + hid;
    float creg = __half2float(g_c016[b8 * HDIM + hb]);
    float bias4[4];
#pragma unroll
    for (int q = 0; q < 4; q++) bias4[q] = g_bias[q * HDIM + hb];

    // ldmatrix lane addressing (validated in R8)
    const int a_r = (lane & 7) + ((lane & 8) ? 8 : 0);
    const int a_c = (lane & 16) ? 8 : 0;
    const int gr  = lane >> 3;
    const int b_r = ((gr & 2) ? 8 : 0) + (lane & 7);
    const int b_c = (gr & 1) ? 8 : 0;

    const size_t y_sz  = (size_t)T_STEPS * BATCH * HDIM;
    const size_t bh_sz = (size_t)BATCH * HDIM;

    __syncthreads();   // wih_s ready

    float acc[2][4][4];

    // stage x[t] slice into this warp's buffer (LDG -> STS, no sync)
    auto x_stage = [&](int t) {
        const __half* xsrc = g_x16 + (size_t)t * BATCH * IDIM;
#pragma unroll
        for (int j = 0; j < 16; j++) {
            int idx = lane + j * 32;
            int row = idx >> 4;
            int col = idx & 15;
            uint4 v = *(const uint4*)&xsrc[(size_t)row * IDIM + kbase + col * 8];
            *(uint4*)&h_w[row * HWP + col * 8] = v;
        }
    };

    // x-mma over the staged buffer, zeroing acc first (assumes the STS above
    // are already ordered by an intervening barrier or syncwarp)
    auto x_mma = [&]() {
#pragma unroll
        for (int mt = 0; mt < 2; mt++)
#pragma unroll
            for (int nt = 0; nt < 4; nt++)
#pragma unroll
                for (int e = 0; e < 4; e++) acc[mt][nt][e] = 0.f;
#pragma unroll
        for (int ki = 0; ki < 8; ki++) {
            int kk = ki * 16;
            unsigned af[2][4];
#pragma unroll
            for (int mt = 0; mt < 2; mt++) {
                unsigned addr = smem_u32(&wih_s[(mt * 16 + a_r) * WIHP
                                                + kbase + kk + a_c]);
                ldsm_x4(af[mt][0], af[mt][1], af[mt][2], af[mt][3], addr);
            }
            unsigned bf[4][2];
#pragma unroll
            for (int ntp = 0; ntp < 4; ntp += 2) {
                unsigned addr = smem_u32(&h_w[(ntp * 8 + b_r) * HWP + kk + b_c]);
                ldsm_x4(bf[ntp][0], bf[ntp][1], bf[ntp + 1][0], bf[ntp + 1][1], addr);
            }
#pragma unroll
            for (int mt = 0; mt < 2; mt++)
#pragma unroll
                for (int nt = 0; nt < 4; nt++)
                    mma_m16n8k16(acc[mt][nt][0], acc[mt][nt][1],
                                 acc[mt][nt][2], acc[mt][nt][3],
                                 af[mt][0], af[mt][1], af[mt][2], af[mt][3],
                                 bf[nt][0], bf[nt][1]);
        }
        __syncwarp();   // buffer free for next staging
    };

    // t=0 x contribution (no dependency)
    x_stage(0);
    __syncwarp();
    x_mma();

    for (int t = 0; t < T_STEPS; t++) {
        // stage h(t-1) into warp buffer
        const __half* hsrc = (t == 0) ? g_h016
                                      : (g_hrelay + (size_t)(t - 1) * bh_sz);
#pragma unroll
        for (int j = 0; j < 16; j++) {
            int idx = lane + j * 32;
            int row = idx >> 4;
            int col = idx & 15;
            uint4 v = *(const uint4*)&hsrc[(size_t)row * HDIM + kbase + col * 8];
            *(uint4*)&h_w[row * HWP + col * 8] = v;
        }
        __syncwarp();

        // h-mma accumulating on top of the x contribution
#pragma unroll
        for (int ki = 0; ki < 8; ki++) {
            int kk = ki * 16;
            unsigned bf[4][2];
#pragma unroll
            for (int ntp = 0; ntp < 4; ntp += 2) {
                unsigned addr = smem_u32(&h_w[(ntp * 8 + b_r) * HWP + kk + b_c]);
                ldsm_x4(bf[ntp][0], bf[ntp][1], bf[ntp + 1][0], bf[ntp + 1][1], addr);
            }
#pragma unroll
            for (int mt = 0; mt < 2; mt++)
#pragma unroll
                for (int nt = 0; nt < 4; nt++)
                    mma_m16n8k16(acc[mt][nt][0], acc[mt][nt][1],
                                 acc[mt][nt][2], acc[mt][nt][3],
                                 a_frag[ki][mt][0], a_frag[ki][mt][1],
                                 a_frag[ki][mt][2], a_frag[ki][mt][3],
                                 bf[nt][0], bf[nt][1]);
        }

        // store partial tile
        float* pw = part + w * PBUF;
#pragma unroll
        for (int mt = 0; mt < 2; mt++)
#pragma unroll
            for (int nt = 0; nt < 4; nt++) {
                int row = mt * 16 + g;
                int col = nt * 8 + coff4;
                *(float2*)&pw[row * PSTR + col]       = make_float2(acc[mt][nt][0], acc[mt][nt][1]);
                *(float2*)&pw[(row + 8) * PSTR + col] = make_float2(acc[mt][nt][2], acc[mt][nt][3]);
            }
        __syncthreads();

        // issue x(t+1) staging NOW — its LDG latency hides under the reduce
        if (t < T_STEPS - 1) x_stage(t + 1);

        // fused reduce + bias + pointwise
        float gate[4] = {bias4[0], bias4[1], bias4[2], bias4[3]};
#pragma unroll
        for (int q = 0; q < 4; q++) {
            int row = q * 8 + hid;
#pragma unroll
            for (int j = 0; j < 8; j++)
                gate[q] += part[j * PBUF + row * PSTR + b8];
        }
        float si = 1.f / (1.f + expf(-gate[0]));
        float sf = 1.f / (1.f + expf(-gate[1]));
        float tg = tanhf(gate[2]);
        float so = 1.f / (1.f + expf(-gate[3]));
        float cnew = sf * creg + si * tg;
        float hnew = so * tanhf(cnew);
        __half h16 = __float2half(hnew);
        __half c16 = __float2half(cnew);
        creg = __half2float(c16);

        size_t idx = ((size_t)t * BATCH + b8) * HDIM + hb;
        g_hrelay[idx] = h16;

        float hf = __half2float(h16);
        if (dt == 0)      ((__half*)out)[idx] = h16;
        else if (dt == 1) ((__nv_bfloat16*)out)[idx] = __float2bfloat16(hf);
        else              ((float*)out)[idx] = hf;

        if (t == T_STEPS - 1) {
            size_t hidx = y_sz + (size_t)b8 * HDIM + hb;
            size_t cidx = hidx + bh_sz;
            float cf = __half2float(c16);
            if (dt == 0) {
                ((__half*)out)[hidx] = h16;
                ((__half*)out)[cidx] = c16;
            } else if (dt == 1) {
                ((__nv_bfloat16*)out)[hidx] = __float2bfloat16(hf);
                ((__nv_bfloat16*)out)[cidx] = __float2bfloat16(cf);
            } else {
                ((float*)out)[hidx] = hf;
                ((float*)out)[cidx] = cf;
            }
        }

        // barrier: syncthreads orders ALL threads' h stores before tid0's
        // release-arrival (publication pattern); x-mma fills the wait window;
        // acquire-poll detects; final syncthreads releases the block.
        if (t < T_STEPS - 1) {
            __syncthreads();
            if (tid == 0)
                asm volatile("red.release.gpu.global.add.u32 [%0], %1;"
                             :: "l"(&g_bar), "r"(1u) : "memory");
            x_mma();                       // wait-window work (x for t+1)
            if (tid == 0) {
                unsigned target = (unsigned)(t + 1) * NBLK;
                unsigned v, spins = 0;
                do {
                    asm volatile("ld.acquire.gpu.global.u32 %0, [%1];"
                                 : "=r"(v) : "l"(&g_bar) : "memory");
                    if (v >= target) break;
                } while (++spins < 4000000u);   // escape hatch
            }
            __syncthreads();
        }
    }
}

// ---------------- launch ----------------
extern "C" void kernel_launch(void* const* d_in, const int* in_sizes, int n_in,
                              void* d_out, int out_size)
{
    const void*  x   = d_in[0];
    const void*  h0  = d_in[1];
    const void*  c0  = d_in[2];
    const float* wih = (const float*)d_in[3];
    const float* whh = (const float*)d_in[4];
    const float* bih = (const float*)d_in[5];
    const float* bhh = (const float*)d_in[6];

    cudaFuncSetAttribute(lstm_kernel,
                         cudaFuncAttributeMaxDynamicSharedMemorySize,
                         SMEM_BYTES);

    detect_kernel<<<1, 256>>>(x);
    prep_kernel<<<1024, 256>>>(wih, whh, bih, bhh);
    convert_kernel<<<2048, 256>>>(x, h0, c0);

    lstm_kernel<<<NBLK, 256, SMEM_BYTES>>>(d_out);
}